// round 4
// baseline (speedup 1.0000x reference)
#include <cuda_runtime.h>
#include <math.h>

#define EDGES 65536
#define NATOM 2048
#define KTOT 69
#define KPAD 84          // padded k-slots: 12 comp-pure groups of 7
#define NFEAT 216
#define NELEM 94
#define EMBD 16
#define H1D 256
#define H2D 128
#define MAXG 256
#define TILE 16
#define PAD 18           // TILE + 2, even (8B-aligned rows)

// ---------------- scratch ----------------
__device__ __align__(16) float d_radialT[120 * EDGES];   // [m][e], m = rad*5+comp
__device__ __align__(16) float d_gijT[KTOT * EDGES];     // [k][e]
__device__ __align__(16) float d_feat[NATOM * NFEAT];
__device__ float d_embS[NELEM * EMBD];
__device__ __align__(16) float d_B[(size_t)NELEM * NFEAT * H1D]; // [s][f][o]
__device__ int   d_seg[NATOM + 1];
__device__ int   d_atom_order[NATOM];
__device__ int   d_grp_s[MAXG], d_grp_start[MAXG], d_grp_cnt[MAXG];
__device__ int   d_ngroups;
__device__ double d_partial[MAXG];

// ---------------- packed fp32x2 helpers ----------------
typedef unsigned long long u64;

__device__ __forceinline__ u64 splat2(float v) {
    u64 r; unsigned int u = __float_as_uint(v);
    asm("mov.b64 %0, {%1, %1};" : "=l"(r) : "r"(u));
    return r;
}
__device__ __forceinline__ void unpack2(u64 v, float& a, float& b) {
    unsigned int x, y;
    asm("mov.b64 {%0, %1}, %2;" : "=r"(x), "=r"(y) : "l"(v));
    a = __uint_as_float(x); b = __uint_as_float(y);
}
__device__ __forceinline__ void fma2(u64& d, u64 a, u64 b) {
    asm("fma.rn.f32x2 %0, %1, %2, %0;" : "+l"(d) : "l"(a), "l"(b));
}

__device__ __forceinline__ float silu(float x) {
    return __fdividef(x, 1.0f + __expf(-x));
}

__device__ constexpr float ffact(int n) {
    return (n <= 1) ? 1.0f : (float)n * ffact(n - 1);
}

// ============================================================================
// per-edge radial MLP (f32x2) + angular factors ; transposed coalesced outputs
// ============================================================================
__global__ void __launch_bounds__(128, 5) k_edge(
    const float* __restrict__ rij,
    const float* __restrict__ Wr1, const float* __restrict__ br1,
    const float* __restrict__ Wr2, const float* __restrict__ br2)
{
    __shared__ __align__(16) float sW1[24 * 64];
    __shared__ __align__(16) float sB1[64];
    __shared__ __align__(16) float sW2[64 * 120];
    __shared__ __align__(16) float sB2[120];
    int tid = threadIdx.x;
    for (int i = tid; i < 24 * 64; i += 128) sW1[i] = Wr1[i];
    for (int i = tid; i < 64;      i += 128) sB1[i] = br1[i];
    for (int i = tid; i < 64 * 120; i += 128) sW2[i] = Wr2[i];
    for (int i = tid; i < 120;     i += 128) sB2[i] = br2[i];
    __syncthreads();

    int e = blockIdx.x * 128 + tid;

    float x = rij[e * 3 + 0], y = rij[e * 3 + 1], z = rij[e * 3 + 2];
    float r = sqrtf(x * x + y * y + z * z);
    float inv = 1.0f / r;
    float ux = x * inv, uy = y * inv, uz = z * inv;

    float rc = fminf(r, 6.0f);
    float fc = 0.5f * (cospif(rc * (1.0f / 6.0f)) + 1.0f);

    float basis[24];
#pragma unroll
    for (int i = 0; i < 24; i++) {
        float d = r - (float)i * (6.0f / 23.0f);
        basis[i] = __expf(-d * d * 8.0f) * fc;
    }

    // angular factors (coalesced per k-row)
    {
        float px[5], py[5], pz[5];
        px[0]=1.0f; px[1]=ux+1e-12f; px[2]=px[1]*px[1]; px[3]=px[2]*px[1]; px[4]=px[2]*px[2];
        py[0]=1.0f; py[1]=uy+1e-12f; py[2]=py[1]*py[1]; py[3]=py[2]*py[1]; py[4]=py[2]*py[2];
        pz[0]=1.0f; pz[1]=uz+1e-12f; pz[2]=pz[1]*pz[1]; pz[3]=pz[2]*pz[1]; pz[4]=pz[2]*pz[2];
        int k = 0;
#pragma unroll
        for (int zz = 1; zz <= 4; zz++) {
#pragma unroll
            for (int n = 0; n <= zz; n++) {
#pragma unroll
                for (int lx = 0; lx <= n; lx++) {
#pragma unroll
                    for (int ly = 0; ly <= n - lx; ly++) {
                        int lz = n - lx - ly;
                        float fn = ffact(zz) / (ffact(zz - n) * ffact(lx) * ffact(ly) * ffact(lz));
                        d_gijT[(size_t)k * EDGES + e] = px[lx] * py[ly] * pz[lz] * fn;
                        k++;
                    }
                }
            }
        }
    }

    // layer 1: 24 -> 64 via FFMA2
    float h[64];
#pragma unroll
    for (int c8 = 0; c8 < 8; c8++) {
        const u64* bb = (const u64*)&sB1[c8 * 8];
        u64 a0 = bb[0], a1 = bb[1], a2 = bb[2], a3 = bb[3];
#pragma unroll
        for (int i = 0; i < 24; i++) {
            u64 bs = splat2(basis[i]);
            const ulonglong2* w = (const ulonglong2*)&sW1[i * 64 + c8 * 8];
            ulonglong2 w01 = w[0], w23 = w[1];
            fma2(a0, bs, w01.x); fma2(a1, bs, w01.y);
            fma2(a2, bs, w23.x); fma2(a3, bs, w23.y);
        }
        float f0, f1;
        unpack2(a0, f0, f1); h[c8*8+0] = silu(f0); h[c8*8+1] = silu(f1);
        unpack2(a1, f0, f1); h[c8*8+2] = silu(f0); h[c8*8+3] = silu(f1);
        unpack2(a2, f0, f1); h[c8*8+4] = silu(f0); h[c8*8+5] = silu(f1);
        unpack2(a3, f0, f1); h[c8*8+6] = silu(f0); h[c8*8+7] = silu(f1);
    }

    // layer 2: 64 -> 120 in 15 chunks of 8 outputs; coalesced transposed stores
#pragma unroll 1
    for (int c8 = 0; c8 < 15; c8++) {
        const u64* bb = (const u64*)&sB2[c8 * 8];
        u64 a0 = bb[0], a1 = bb[1], a2 = bb[2], a3 = bb[3];
#pragma unroll
        for (int j = 0; j < 64; j++) {
            u64 hs = splat2(h[j]);
            const ulonglong2* w = (const ulonglong2*)&sW2[j * 120 + c8 * 8];
            ulonglong2 w01 = w[0], w23 = w[1];
            fma2(a0, hs, w01.x); fma2(a1, hs, w01.y);
            fma2(a2, hs, w23.x); fma2(a3, hs, w23.y);
        }
        float f0, f1, f2, f3, f4, f5, f6, f7;
        unpack2(a0, f0, f1); unpack2(a1, f2, f3);
        unpack2(a2, f4, f5); unpack2(a3, f6, f7);
        float* ob = &d_radialT[(size_t)(c8 * 8) * EDGES + e];
        ob[0 * EDGES] = silu(f0); ob[1 * (size_t)EDGES] = silu(f1);
        ob[2 * (size_t)EDGES] = silu(f2); ob[3 * (size_t)EDGES] = silu(f3);
        ob[4 * (size_t)EDGES] = silu(f4); ob[5 * (size_t)EDGES] = silu(f5);
        ob[6 * (size_t)EDGES] = silu(f6); ob[7 * (size_t)EDGES] = silu(f7);
    }
}

// ============================================================================
// segment starts
// ============================================================================
__global__ void k_seg(const int* __restrict__ fai)
{
    int e = blockIdx.x * 256 + threadIdx.x;
    if (e >= EDGES) return;
    int f = fai[e];
    int fp = (e == 0) ? -1 : fai[e - 1];
    for (int a = fp + 1; a <= f; a++) d_seg[a] = e;
    if (e == EDGES - 1) {
        for (int a = f + 1; a <= NATOM; a++) d_seg[a] = EDGES;
    }
}

// ============================================================================
// per-atom segmented reduction: register-tiled outer product (4 rad x 7 k)
// padded k layout (comp-pure groups of 7):
//   kp 0..3   -> k 0..3   (z=1, comp1) ; kp 4..6 dummy
//   kp 7..16  -> k 4..13  (z=2, comp2) ; kp 17..20 dummy
//   kp 21..40 -> k 14..33 (z=3, comp3) ; kp 41 dummy
//   kp 42..76 -> k 34..68 (z=4, comp4)
//   kp 77     -> two-body (comp0, g=1); kp 78..83 dummy
// ============================================================================
template <int Z>
__device__ __forceinline__ float zsum(const float* sgi, int rad, int sflag, int koff) {
    float sum = 0.0f;
    int idx = 0;
#pragma unroll
    for (int n = 0; n <= Z; n++) {
        float lam = (n & 1) ? -1.0f : 1.0f;
#pragma unroll
        for (int lx = 0; lx <= n; lx++) {
#pragma unroll
            for (int ly = 0; ly <= n - lx; ly++) {
                float g = sgi[rad * KPAD + koff + idx];
                float g2 = g * g;
                sum += sflag ? g2 * lam : g2;
                idx++;
            }
        }
    }
    return sum * (1.0f / (float)(1 << (Z - 1)));
}

__global__ void __launch_bounds__(128) k_atom()
{
    __shared__ __align__(16) float sr[120 * PAD];   // radial rows m=rad*5+comp
    __shared__ __align__(16) float sg[KPAD * PAD];  // padded g rows
    __shared__ float sgi[24 * KPAD];

    int a = blockIdx.x;
    int tid = threadIdx.x;
    int lo = d_seg[a], hi = d_seg[a + 1];

    // compute-thread tile metadata: 72 threads = 12 kgroups x 6 radgroups
    int kg = tid / 6;        // 0..11 (only tid<72 valid)
    int rg = tid - kg * 6;   // 0..5
    int comp = (kg == 0) ? 1 : (kg < 3) ? 2 : (kg < 6) ? 3 : (kg < 11) ? 4 : 0;
    bool compute = (tid < 72);

    // byte offsets of the 4 radial rows and 7 g rows
    int rrow[4], grow[7];
#pragma unroll
    for (int i = 0; i < 4; i++) rrow[i] = ((rg * 4 + i) * 5 + comp) * PAD;
#pragma unroll
    for (int j = 0; j < 7; j++) grow[j] = (kg * 7 + j) * PAD;

    u64 acc[28];
#pragma unroll
    for (int q = 0; q < 28; q++) acc[q] = 0ull;

    for (int e0 = lo; e0 < hi; e0 += TILE) {
        // stage radial rows: 120*16 = 1920 elems
#pragma unroll 1
        for (int s = 0; s < 15; s++) {
            int i = tid + s * 128;
            int m = i >> 4, ee = i & 15;
            int e = e0 + ee;
            sr[m * PAD + ee] = (e < hi) ? d_radialT[(size_t)m * EDGES + e] : 0.0f;
        }
        // stage padded g rows: 84*16 = 1344 elems
#pragma unroll 1
        for (int s = 0; s < 11; s++) {
            int i = tid + s * 128;
            if (i < KPAD * 16) {
                int kp = i >> 4, ee = i & 15;
                int e = e0 + ee;
                float v = 0.0f;
                if (e < hi) {
                    if (kp < 4)       v = d_gijT[(size_t)kp * EDGES + e];
                    else if (kp < 7)  v = 0.0f;
                    else if (kp < 17) v = d_gijT[(size_t)(kp - 3) * EDGES + e];
                    else if (kp < 21) v = 0.0f;
                    else if (kp < 41) v = d_gijT[(size_t)(kp - 7) * EDGES + e];
                    else if (kp < 42) v = 0.0f;
                    else if (kp < 77) v = d_gijT[(size_t)(kp - 8) * EDGES + e];
                    else if (kp == 77) v = 1.0f;
                } else if (kp == 77) {
                    v = 1.0f;   // two-body row: padded radial=0 nullifies
                }
                sg[kp * PAD + ee] = v;
            }
        }
        __syncthreads();

        if (compute) {
#pragma unroll
            for (int p = 0; p < 8; p++) {
                u64 rv[4], gv[7];
#pragma unroll
                for (int i = 0; i < 4; i++) rv[i] = *(const u64*)&sr[rrow[i] + 2 * p];
#pragma unroll
                for (int j = 0; j < 7; j++) gv[j] = *(const u64*)&sg[grow[j] + 2 * p];
#pragma unroll
                for (int i = 0; i < 4; i++)
#pragma unroll
                    for (int j = 0; j < 7; j++)
                        fma2(acc[i * 7 + j], rv[i], gv[j]);
            }
        }
        __syncthreads();
    }

    if (compute) {
#pragma unroll
        for (int i = 0; i < 4; i++) {
#pragma unroll
            for (int j = 0; j < 7; j++) {
                float l0, l1; unpack2(acc[i * 7 + j], l0, l1);
                sgi[(rg * 4 + i) * KPAD + kg * 7 + j] = l0 + l1;
            }
        }
    }
    __syncthreads();

    // descriptor assembly: 216 feats with 128 threads (2 passes)
    for (int f = tid; f < NFEAT; f += 128) {
        float v;
        if (f < 24) v = sgi[f * KPAD + 77];
        else {
            int t = f - 24;
            int iz = t / 48;
            int sflag = (t / 24) & 1;
            int rad = t % 24;
            if (iz == 0)      v = zsum<1>(sgi, rad, sflag, 0);
            else if (iz == 1) v = zsum<2>(sgi, rad, sflag, 7);
            else if (iz == 2) v = zsum<3>(sgi, rad, sflag, 21);
            else              v = zsum<4>(sgi, rad, sflag, 42);
        }
        d_feat[a * NFEAT + f] = v;
    }
}

// ============================================================================
// species embedding + collapsed first-layer weights B[s][f][o]
// ============================================================================
__global__ void k_embS(const float* __restrict__ Ws1, const float* __restrict__ bs1,
                       const float* __restrict__ Ws2, const float* __restrict__ bs2)
{
    int s = blockIdx.x;
    int t = threadIdx.x;   // 32
    __shared__ float hh[32];
    hh[t] = silu(Ws1[s * 32 + t] + bs1[t]);
    __syncwarp();
    if (t < EMBD) {
        float a = bs2[t];
#pragma unroll
        for (int j = 0; j < 32; j++) a += hh[j] * Ws2[j * EMBD + t];
        d_embS[s * EMBD + t] = a;
    }
}

__global__ void __launch_bounds__(256) k_B(const float* __restrict__ Wa1)
{
    int f = blockIdx.x;      // 216
    int tid = threadIdx.x;   // 256
    __shared__ float sW[16 * 256];
    __shared__ float sE[NELEM * EMBD];
    for (int i = tid; i < 16 * 256; i += 256) sW[i] = Wa1[(size_t)(f * 16) * 256 + i];
    for (int i = tid; i < NELEM * EMBD; i += 256) sE[i] = d_embS[i];
    __syncthreads();
#pragma unroll 2
    for (int s = 0; s < NELEM; s++) {
        float acc = 0.0f;
#pragma unroll
        for (int m = 0; m < EMBD; m++) acc += sE[s * EMBD + m] * sW[m * 256 + tid];
        d_B[((size_t)s * NFEAT + f) * H1D + tid] = acc;
    }
}

// ============================================================================
// deterministic species grouping (single block)
// ============================================================================
__global__ void __launch_bounds__(1024) k_group(const int* __restrict__ sp)
{
    __shared__ int cnt[NELEM];
    __shared__ int off[NELEM];
    __shared__ int ssp[NATOM];
    int tid = threadIdx.x;
    if (tid < NELEM) cnt[tid] = 0;
    for (int a = tid; a < NATOM; a += 1024) ssp[a] = sp[a];
    __syncthreads();
    for (int a = tid; a < NATOM; a += 1024) atomicAdd(&cnt[ssp[a]], 1);
    __syncthreads();
    if (tid == 0) {
        int o = 0, ng = 0;
        for (int s = 0; s < NELEM; s++) {
            off[s] = o;
            int c = cnt[s];
            for (int ch = 0; ch < c; ch += 16) {
                d_grp_s[ng] = s; d_grp_start[ng] = o + ch;
                d_grp_cnt[ng] = min(16, c - ch); ng++;
            }
            o += c;
        }
        d_ngroups = ng;
    }
    for (int g = tid; g < MAXG; g += 1024) d_partial[g] = 0.0;
    __syncthreads();
    for (int a = tid; a < NATOM; a += 1024) {
        int s = ssp[a];
        int r = 0;
        for (int j = 0; j < a; j++) r += (ssp[j] == s);
        d_atom_order[off[s] + r] = a;
    }
}

// ============================================================================
// head MLP per species group (<=16 atoms), atoms packed in f32x2 lanes
// ============================================================================
__global__ void __launch_bounds__(256) k_head(
    const float* __restrict__ ba1,
    const float* __restrict__ Wa2, const float* __restrict__ ba2,
    const float* __restrict__ Wa3, const float* __restrict__ ba3)
{
    int g = blockIdx.x;
    if (g >= d_ngroups) return;
    int tid = threadIdx.x;

    __shared__ __align__(16) float sfeatT[NFEAT * 18];   // [f][atom]
    __shared__ __align__(16) float sh1T[H1D * 18];       // [j][atom]
    __shared__ __align__(16) float sh2T[H2D * 18];       // [o][atom]
    __shared__ double se[16];
    __shared__ int satom[16];

    int s = d_grp_s[g], start = d_grp_start[g], cnt = d_grp_cnt[g];
    if (tid < 16) satom[tid] = (tid < cnt) ? d_atom_order[start + tid] : 0;
    __syncthreads();

    for (int i = tid; i < 16 * NFEAT; i += 256) {
        int al = i / NFEAT, f = i - al * NFEAT;
        sfeatT[f * 18 + al] = (al < cnt) ? d_feat[(size_t)satom[al] * NFEAT + f] : 0.0f;
    }
    __syncthreads();

    // layer 1: 216 -> 256 ; thread = output neuron, 16 atoms as 8 pairs
    {
        u64 acc2[8];
        u64 binit = splat2(ba1[tid]);
#pragma unroll
        for (int p = 0; p < 8; p++) acc2[p] = binit;

        const float* Bs = &d_B[((size_t)s * NFEAT) * H1D + tid];
#pragma unroll 8
        for (int f = 0; f < NFEAT; f++) {
            u64 bw = splat2(__ldg(&Bs[(size_t)f * H1D]));
            const u64* fp = (const u64*)&sfeatT[f * 18];
#pragma unroll
            for (int p = 0; p < 8; p++) fma2(acc2[p], fp[p], bw);
        }
#pragma unroll
        for (int p = 0; p < 8; p++) {
            float lo, hi; unpack2(acc2[p], lo, hi);
            sh1T[tid * 18 + 2 * p]     = silu(lo);
            sh1T[tid * 18 + 2 * p + 1] = silu(hi);
        }
    }
    __syncthreads();

    // layer 2: 256 -> 128 ; thread = (out o2, atom-half)
    {
        int o2 = tid & 127;
        int half = tid >> 7;
        u64 acc2[4];
        u64 binit = splat2(ba2[o2]);
#pragma unroll
        for (int p = 0; p < 4; p++) acc2[p] = binit;
#pragma unroll 4
        for (int j = 0; j < H1D; j++) {
            u64 w = splat2(__ldg(&Wa2[j * H2D + o2]));
            const u64* hp = (const u64*)&sh1T[j * 18 + half * 8];
#pragma unroll
            for (int p = 0; p < 4; p++) fma2(acc2[p], hp[p], w);
        }
#pragma unroll
        for (int p = 0; p < 4; p++) {
            float lo, hi; unpack2(acc2[p], lo, hi);
            sh2T[o2 * 18 + half * 8 + 2 * p]     = silu(lo);
            sh2T[o2 * 18 + half * 8 + 2 * p + 1] = silu(hi);
        }
    }
    __syncthreads();

    if (tid < 16) {
        double ev = 0.0;
        if (tid < cnt) {
            float e3 = ba3[0];
#pragma unroll 4
            for (int j = 0; j < H2D; j++) e3 += sh2T[j * 18 + tid] * Wa3[j];
            ev = (double)e3;
        }
        se[tid] = ev;
    }
    __syncthreads();
    if (tid == 0) {
        double ssum = 0.0;
        for (int i = 0; i < 16; i++) ssum += se[i];
        d_partial[g] = ssum;
    }
}

__global__ void k_final(float* out) {
    int lane = threadIdx.x;
    double s = 0.0;
    for (int g = lane; g < MAXG; g += 32) s += d_partial[g];
#pragma unroll
    for (int o = 16; o > 0; o >>= 1) s += __shfl_down_sync(0xffffffffu, s, o);
    if (lane == 0) out[0] = (float)s;
}

// ============================================================================
extern "C" void kernel_launch(void* const* d_in, const int* in_sizes, int n_in,
                              void* d_out, int out_size)
{
    const float* rij = (const float*)d_in[0];
    const float* Wr1 = (const float*)d_in[1];
    const float* br1 = (const float*)d_in[2];
    const float* Wr2 = (const float*)d_in[3];
    const float* br2 = (const float*)d_in[4];
    const float* Ws1 = (const float*)d_in[5];
    const float* bs1 = (const float*)d_in[6];
    const float* Ws2 = (const float*)d_in[7];
    const float* bs2 = (const float*)d_in[8];
    const float* Wa1 = (const float*)d_in[9];
    const float* ba1 = (const float*)d_in[10];
    const float* Wa2 = (const float*)d_in[11];
    const float* ba2 = (const float*)d_in[12];
    const float* Wa3 = (const float*)d_in[13];
    const float* ba3 = (const float*)d_in[14];
    const int* fai = (const int*)d_in[15];
    const int* species = (const int*)d_in[16];
    float* out = (float*)d_out;

    // order chosen so ncu (captures launch #4) profiles k_atom
    k_edge<<<EDGES / 128, 128>>>(rij, Wr1, br1, Wr2, br2);
    k_seg<<<EDGES / 256, 256>>>(fai);
    k_group<<<1, 1024>>>(species);
    k_atom<<<NATOM, 128>>>();
    k_embS<<<NELEM, 32>>>(Ws1, bs1, Ws2, bs2);
    k_B<<<NFEAT, 256>>>(Wa1);
    k_head<<<MAXG, 256>>>(ba1, Wa2, ba2, Wa3, ba3);
    k_final<<<1, 32>>>(out);
}

// round 5
// speedup vs baseline: 1.1544x; 1.1544x over previous
#include <cuda_runtime.h>
#include <math.h>

#define EDGES 65536
#define NATOM 2048
#define KTOT 69
#define KPAD 84          // padded k-slots: 12 comp-pure groups of 7
#define NFEAT 216
#define NELEM 94
#define EMBD 16
#define H1D 256
#define H2D 128
#define MAXG 256
#define TILE 32
#define PAD 34           // TILE + 2, even (8B-aligned rows)

// ---------------- scratch ----------------
__device__ __align__(16) float d_radialT[120 * EDGES];   // [m][e], m = rad*5+comp
__device__ __align__(16) float d_gijT[KTOT * EDGES];     // [k][e]
__device__ __align__(16) float d_feat[NATOM * NFEAT];
__device__ float d_embS[NELEM * EMBD];
__device__ __align__(16) float d_B[(size_t)NELEM * NFEAT * H1D]; // [s][f][o]
__device__ int   d_seg[NATOM + 1];
__device__ int   d_atom_order[NATOM];
__device__ int   d_grp_s[MAXG], d_grp_start[MAXG], d_grp_cnt[MAXG];
__device__ int   d_ngroups;
__device__ double d_partial[MAXG];

// ---------------- packed fp32x2 helpers ----------------
typedef unsigned long long u64;

__device__ __forceinline__ u64 splat2(float v) {
    u64 r; unsigned int u = __float_as_uint(v);
    asm("mov.b64 %0, {%1, %1};" : "=l"(r) : "r"(u));
    return r;
}
__device__ __forceinline__ void unpack2(u64 v, float& a, float& b) {
    unsigned int x, y;
    asm("mov.b64 {%0, %1}, %2;" : "=r"(x), "=r"(y) : "l"(v));
    a = __uint_as_float(x); b = __uint_as_float(y);
}
__device__ __forceinline__ void fma2(u64& d, u64 a, u64 b) {
    asm("fma.rn.f32x2 %0, %1, %2, %0;" : "+l"(d) : "l"(a), "l"(b));
}

__device__ __forceinline__ float silu(float x) {
    return __fdividef(x, 1.0f + __expf(-x));
}

__device__ constexpr float ffact(int n) {
    return (n <= 1) ? 1.0f : (float)n * ffact(n - 1);
}

// ============================================================================
// per-edge radial MLP (f32x2) + angular factors ; transposed coalesced outputs
// ============================================================================
__global__ void __launch_bounds__(128, 5) k_edge(
    const float* __restrict__ rij,
    const float* __restrict__ Wr1, const float* __restrict__ br1,
    const float* __restrict__ Wr2, const float* __restrict__ br2)
{
    __shared__ __align__(16) float sW1[24 * 64];
    __shared__ __align__(16) float sB1[64];
    __shared__ __align__(16) float sW2[64 * 120];
    __shared__ __align__(16) float sB2[120];
    int tid = threadIdx.x;
    for (int i = tid; i < 24 * 64; i += 128) sW1[i] = Wr1[i];
    for (int i = tid; i < 64;      i += 128) sB1[i] = br1[i];
    for (int i = tid; i < 64 * 120; i += 128) sW2[i] = Wr2[i];
    for (int i = tid; i < 120;     i += 128) sB2[i] = br2[i];
    __syncthreads();

    int e = blockIdx.x * 128 + tid;

    float x = rij[e * 3 + 0], y = rij[e * 3 + 1], z = rij[e * 3 + 2];
    float r = sqrtf(x * x + y * y + z * z);
    float inv = 1.0f / r;
    float ux = x * inv, uy = y * inv, uz = z * inv;

    float rc = fminf(r, 6.0f);
    float fc = 0.5f * (cospif(rc * (1.0f / 6.0f)) + 1.0f);

    float basis[24];
#pragma unroll
    for (int i = 0; i < 24; i++) {
        float d = r - (float)i * (6.0f / 23.0f);
        basis[i] = __expf(-d * d * 8.0f) * fc;
    }

    // angular factors (coalesced per k-row)
    {
        float px[5], py[5], pz[5];
        px[0]=1.0f; px[1]=ux+1e-12f; px[2]=px[1]*px[1]; px[3]=px[2]*px[1]; px[4]=px[2]*px[2];
        py[0]=1.0f; py[1]=uy+1e-12f; py[2]=py[1]*py[1]; py[3]=py[2]*py[1]; py[4]=py[2]*py[2];
        pz[0]=1.0f; pz[1]=uz+1e-12f; pz[2]=pz[1]*pz[1]; pz[3]=pz[2]*pz[1]; pz[4]=pz[2]*pz[2];
        int k = 0;
#pragma unroll
        for (int zz = 1; zz <= 4; zz++) {
#pragma unroll
            for (int n = 0; n <= zz; n++) {
#pragma unroll
                for (int lx = 0; lx <= n; lx++) {
#pragma unroll
                    for (int ly = 0; ly <= n - lx; ly++) {
                        int lz = n - lx - ly;
                        float fn = ffact(zz) / (ffact(zz - n) * ffact(lx) * ffact(ly) * ffact(lz));
                        d_gijT[(size_t)k * EDGES + e] = px[lx] * py[ly] * pz[lz] * fn;
                        k++;
                    }
                }
            }
        }
    }

    // layer 1: 24 -> 64 via FFMA2
    float h[64];
#pragma unroll
    for (int c8 = 0; c8 < 8; c8++) {
        const u64* bb = (const u64*)&sB1[c8 * 8];
        u64 a0 = bb[0], a1 = bb[1], a2 = bb[2], a3 = bb[3];
#pragma unroll
        for (int i = 0; i < 24; i++) {
            u64 bs = splat2(basis[i]);
            const ulonglong2* w = (const ulonglong2*)&sW1[i * 64 + c8 * 8];
            ulonglong2 w01 = w[0], w23 = w[1];
            fma2(a0, bs, w01.x); fma2(a1, bs, w01.y);
            fma2(a2, bs, w23.x); fma2(a3, bs, w23.y);
        }
        float f0, f1;
        unpack2(a0, f0, f1); h[c8*8+0] = silu(f0); h[c8*8+1] = silu(f1);
        unpack2(a1, f0, f1); h[c8*8+2] = silu(f0); h[c8*8+3] = silu(f1);
        unpack2(a2, f0, f1); h[c8*8+4] = silu(f0); h[c8*8+5] = silu(f1);
        unpack2(a3, f0, f1); h[c8*8+6] = silu(f0); h[c8*8+7] = silu(f1);
    }

    // layer 2: 64 -> 120 in 15 chunks of 8 outputs; coalesced transposed stores
#pragma unroll 1
    for (int c8 = 0; c8 < 15; c8++) {
        const u64* bb = (const u64*)&sB2[c8 * 8];
        u64 a0 = bb[0], a1 = bb[1], a2 = bb[2], a3 = bb[3];
#pragma unroll
        for (int j = 0; j < 64; j++) {
            u64 hs = splat2(h[j]);
            const ulonglong2* w = (const ulonglong2*)&sW2[j * 120 + c8 * 8];
            ulonglong2 w01 = w[0], w23 = w[1];
            fma2(a0, hs, w01.x); fma2(a1, hs, w01.y);
            fma2(a2, hs, w23.x); fma2(a3, hs, w23.y);
        }
        float f0, f1, f2, f3, f4, f5, f6, f7;
        unpack2(a0, f0, f1); unpack2(a1, f2, f3);
        unpack2(a2, f4, f5); unpack2(a3, f6, f7);
        float* ob = &d_radialT[(size_t)(c8 * 8) * EDGES + e];
        ob[0 * EDGES] = silu(f0); ob[1 * (size_t)EDGES] = silu(f1);
        ob[2 * (size_t)EDGES] = silu(f2); ob[3 * (size_t)EDGES] = silu(f3);
        ob[4 * (size_t)EDGES] = silu(f4); ob[5 * (size_t)EDGES] = silu(f5);
        ob[6 * (size_t)EDGES] = silu(f6); ob[7 * (size_t)EDGES] = silu(f7);
    }
}

// ============================================================================
// segment starts
// ============================================================================
__global__ void k_seg(const int* __restrict__ fai)
{
    int e = blockIdx.x * 256 + threadIdx.x;
    if (e >= EDGES) return;
    int f = fai[e];
    int fp = (e == 0) ? -1 : fai[e - 1];
    for (int a = fp + 1; a <= f; a++) d_seg[a] = e;
    if (e == EDGES - 1) {
        for (int a = f + 1; a <= NATOM; a++) d_seg[a] = EDGES;
    }
}

// ============================================================================
// per-atom segmented reduction: register-tiled outer product (4 rad x 7 k)
// staging fully unrolled -> ~50 LDGs in flight (fixes MLP=1 DRAM serialization)
// ============================================================================
template <int Z>
__device__ __forceinline__ float zsum(const float* sgi, int rad, int sflag, int koff) {
    float sum = 0.0f;
    int idx = 0;
#pragma unroll
    for (int n = 0; n <= Z; n++) {
        float lam = (n & 1) ? -1.0f : 1.0f;
#pragma unroll
        for (int lx = 0; lx <= n; lx++) {
#pragma unroll
            for (int ly = 0; ly <= n - lx; ly++) {
                float g = sgi[rad * KPAD + koff + idx];
                float g2 = g * g;
                sum += sflag ? g2 * lam : g2;
                idx++;
            }
        }
    }
    return sum * (1.0f / (float)(1 << (Z - 1)));
}

__global__ void __launch_bounds__(128) k_atom()
{
    __shared__ __align__(16) float sr[120 * PAD];   // radial rows m=rad*5+comp
    __shared__ __align__(16) float sg[KPAD * PAD];  // padded g rows
    __shared__ float sgi[24 * KPAD];

    int a = blockIdx.x;
    int tid = threadIdx.x;
    int lo = d_seg[a], hi = d_seg[a + 1];

    // compute-thread tile metadata: 72 threads = 12 kgroups x 6 radgroups
    int kg = tid / 6;        // 0..11 (only tid<72 valid)
    int rg = tid - kg * 6;   // 0..5
    int comp = (kg == 0) ? 1 : (kg < 3) ? 2 : (kg < 6) ? 3 : (kg < 11) ? 4 : 0;
    bool compute = (tid < 72);

    int rrow[4], grow[7];
#pragma unroll
    for (int i = 0; i < 4; i++) rrow[i] = ((rg * 4 + i) * 5 + comp) * PAD;
#pragma unroll
    for (int j = 0; j < 7; j++) grow[j] = (kg * 7 + j) * PAD;

    u64 acc[28];
#pragma unroll
    for (int q = 0; q < 28; q++) acc[q] = 0ull;

    for (int e0 = lo; e0 < hi; e0 += TILE) {
        // stage radial rows: 120*32 = 3840 elems, 30 independent LDGs in flight
#pragma unroll
        for (int s = 0; s < 30; s++) {
            int i = tid + s * 128;
            int m = i >> 5, ee = i & 31;
            int e = e0 + ee;
            sr[m * PAD + ee] = (e < hi) ? d_radialT[(size_t)m * EDGES + e] : 0.0f;
        }
        // stage padded g rows: 84*32 = 2688 elems, 21 independent LDGs
#pragma unroll
        for (int s = 0; s < 21; s++) {
            int i = tid + s * 128;
            int kp = i >> 5, ee = i & 31;
            int e = e0 + ee;
            float v = 0.0f;
            if (e < hi) {
                if (kp < 4)       v = d_gijT[(size_t)kp * EDGES + e];
                else if (kp < 7)  v = 0.0f;
                else if (kp < 17) v = d_gijT[(size_t)(kp - 3) * EDGES + e];
                else if (kp < 21) v = 0.0f;
                else if (kp < 41) v = d_gijT[(size_t)(kp - 7) * EDGES + e];
                else if (kp < 42) v = 0.0f;
                else if (kp < 77) v = d_gijT[(size_t)(kp - 8) * EDGES + e];
                else if (kp == 77) v = 1.0f;
            } else if (kp == 77) {
                v = 1.0f;   // two-body row: padded radial=0 nullifies
            }
            sg[kp * PAD + ee] = v;
        }
        __syncthreads();

        if (compute) {
#pragma unroll
            for (int p = 0; p < 16; p++) {
                u64 rv[4], gv[7];
#pragma unroll
                for (int i = 0; i < 4; i++) rv[i] = *(const u64*)&sr[rrow[i] + 2 * p];
#pragma unroll
                for (int j = 0; j < 7; j++) gv[j] = *(const u64*)&sg[grow[j] + 2 * p];
#pragma unroll
                for (int i = 0; i < 4; i++)
#pragma unroll
                    for (int j = 0; j < 7; j++)
                        fma2(acc[i * 7 + j], rv[i], gv[j]);
            }
        }
        __syncthreads();
    }

    if (compute) {
#pragma unroll
        for (int i = 0; i < 4; i++) {
#pragma unroll
            for (int j = 0; j < 7; j++) {
                float l0, l1; unpack2(acc[i * 7 + j], l0, l1);
                sgi[(rg * 4 + i) * KPAD + kg * 7 + j] = l0 + l1;
            }
        }
    }
    __syncthreads();

    // descriptor assembly: 216 feats with 128 threads (2 passes)
    for (int f = tid; f < NFEAT; f += 128) {
        float v;
        if (f < 24) v = sgi[f * KPAD + 77];
        else {
            int t = f - 24;
            int iz = t / 48;
            int sflag = (t / 24) & 1;
            int rad = t % 24;
            if (iz == 0)      v = zsum<1>(sgi, rad, sflag, 0);
            else if (iz == 1) v = zsum<2>(sgi, rad, sflag, 7);
            else if (iz == 2) v = zsum<3>(sgi, rad, sflag, 21);
            else              v = zsum<4>(sgi, rad, sflag, 42);
        }
        d_feat[a * NFEAT + f] = v;
    }
}

// ============================================================================
// species embedding + collapsed first-layer weights B[s][f][o]
// ============================================================================
__global__ void k_embS(const float* __restrict__ Ws1, const float* __restrict__ bs1,
                       const float* __restrict__ Ws2, const float* __restrict__ bs2)
{
    int s = blockIdx.x;
    int t = threadIdx.x;   // 32
    __shared__ float hh[32];
    hh[t] = silu(Ws1[s * 32 + t] + bs1[t]);
    __syncwarp();
    if (t < EMBD) {
        float a = bs2[t];
#pragma unroll
        for (int j = 0; j < 32; j++) a += hh[j] * Ws2[j * EMBD + t];
        d_embS[s * EMBD + t] = a;
    }
}

__global__ void __launch_bounds__(256) k_B(const float* __restrict__ Wa1)
{
    int f = blockIdx.x;      // 216
    int tid = threadIdx.x;   // 256
    __shared__ float sW[16 * 256];
    __shared__ float sE[NELEM * EMBD];
    for (int i = tid; i < 16 * 256; i += 256) sW[i] = Wa1[(size_t)(f * 16) * 256 + i];
    for (int i = tid; i < NELEM * EMBD; i += 256) sE[i] = d_embS[i];
    __syncthreads();
#pragma unroll 2
    for (int s = 0; s < NELEM; s++) {
        float acc = 0.0f;
#pragma unroll
        for (int m = 0; m < EMBD; m++) acc += sE[s * EMBD + m] * sW[m * 256 + tid];
        d_B[((size_t)s * NFEAT + f) * H1D + tid] = acc;
    }
}

// ============================================================================
// deterministic species grouping (single block)
// ============================================================================
__global__ void __launch_bounds__(1024) k_group(const int* __restrict__ sp)
{
    __shared__ int cnt[NELEM];
    __shared__ int off[NELEM];
    __shared__ int ssp[NATOM];
    int tid = threadIdx.x;
    if (tid < NELEM) cnt[tid] = 0;
    for (int a = tid; a < NATOM; a += 1024) ssp[a] = sp[a];
    __syncthreads();
    for (int a = tid; a < NATOM; a += 1024) atomicAdd(&cnt[ssp[a]], 1);
    __syncthreads();
    if (tid == 0) {
        int o = 0, ng = 0;
        for (int s = 0; s < NELEM; s++) {
            off[s] = o;
            int c = cnt[s];
            for (int ch = 0; ch < c; ch += 16) {
                d_grp_s[ng] = s; d_grp_start[ng] = o + ch;
                d_grp_cnt[ng] = min(16, c - ch); ng++;
            }
            o += c;
        }
        d_ngroups = ng;
    }
    for (int g = tid; g < MAXG; g += 1024) d_partial[g] = 0.0;
    __syncthreads();
    for (int a = tid; a < NATOM; a += 1024) {
        int s = ssp[a];
        int r = 0;
        for (int j = 0; j < a; j++) r += (ssp[j] == s);
        d_atom_order[off[s] + r] = a;
    }
}

// ============================================================================
// head MLP per species group (<=16 atoms), atoms packed in f32x2 lanes
// ============================================================================
__global__ void __launch_bounds__(256) k_head(
    const float* __restrict__ ba1,
    const float* __restrict__ Wa2, const float* __restrict__ ba2,
    const float* __restrict__ Wa3, const float* __restrict__ ba3)
{
    int g = blockIdx.x;
    if (g >= d_ngroups) return;
    int tid = threadIdx.x;

    __shared__ __align__(16) float sfeatT[NFEAT * 18];   // [f][atom]
    __shared__ __align__(16) float sh1T[H1D * 18];       // [j][atom]
    __shared__ __align__(16) float sh2T[H2D * 18];       // [o][atom]
    __shared__ double se[16];
    __shared__ int satom[16];

    int s = d_grp_s[g], start = d_grp_start[g], cnt = d_grp_cnt[g];
    if (tid < 16) satom[tid] = (tid < cnt) ? d_atom_order[start + tid] : 0;
    __syncthreads();

    for (int i = tid; i < 16 * NFEAT; i += 256) {
        int al = i / NFEAT, f = i - al * NFEAT;
        sfeatT[f * 18 + al] = (al < cnt) ? d_feat[(size_t)satom[al] * NFEAT + f] : 0.0f;
    }
    __syncthreads();

    // layer 1: 216 -> 256 ; thread = output neuron, 16 atoms as 8 pairs
    {
        u64 acc2[8];
        u64 binit = splat2(ba1[tid]);
#pragma unroll
        for (int p = 0; p < 8; p++) acc2[p] = binit;

        const float* Bs = &d_B[((size_t)s * NFEAT) * H1D + tid];
#pragma unroll 8
        for (int f = 0; f < NFEAT; f++) {
            u64 bw = splat2(__ldg(&Bs[(size_t)f * H1D]));
            const u64* fp = (const u64*)&sfeatT[f * 18];
#pragma unroll
            for (int p = 0; p < 8; p++) fma2(acc2[p], fp[p], bw);
        }
#pragma unroll
        for (int p = 0; p < 8; p++) {
            float lo, hi; unpack2(acc2[p], lo, hi);
            sh1T[tid * 18 + 2 * p]     = silu(lo);
            sh1T[tid * 18 + 2 * p + 1] = silu(hi);
        }
    }
    __syncthreads();

    // layer 2: 256 -> 128 ; thread = (out o2, atom-half)
    {
        int o2 = tid & 127;
        int half = tid >> 7;
        u64 acc2[4];
        u64 binit = splat2(ba2[o2]);
#pragma unroll
        for (int p = 0; p < 4; p++) acc2[p] = binit;
#pragma unroll 4
        for (int j = 0; j < H1D; j++) {
            u64 w = splat2(__ldg(&Wa2[j * H2D + o2]));
            const u64* hp = (const u64*)&sh1T[j * 18 + half * 8];
#pragma unroll
            for (int p = 0; p < 4; p++) fma2(acc2[p], hp[p], w);
        }
#pragma unroll
        for (int p = 0; p < 4; p++) {
            float lo, hi; unpack2(acc2[p], lo, hi);
            sh2T[o2 * 18 + half * 8 + 2 * p]     = silu(lo);
            sh2T[o2 * 18 + half * 8 + 2 * p + 1] = silu(hi);
        }
    }
    __syncthreads();

    if (tid < 16) {
        double ev = 0.0;
        if (tid < cnt) {
            float e3 = ba3[0];
#pragma unroll 4
            for (int j = 0; j < H2D; j++) e3 += sh2T[j * 18 + tid] * Wa3[j];
            ev = (double)e3;
        }
        se[tid] = ev;
    }
    __syncthreads();
    if (tid == 0) {
        double ssum = 0.0;
        for (int i = 0; i < 16; i++) ssum += se[i];
        d_partial[g] = ssum;
    }
}

__global__ void k_final(float* out) {
    int lane = threadIdx.x;
    double s = 0.0;
    for (int g = lane; g < MAXG; g += 32) s += d_partial[g];
#pragma unroll
    for (int o = 16; o > 0; o >>= 1) s += __shfl_down_sync(0xffffffffu, s, o);
    if (lane == 0) out[0] = (float)s;
}

// ============================================================================
extern "C" void kernel_launch(void* const* d_in, const int* in_sizes, int n_in,
                              void* d_out, int out_size)
{
    const float* rij = (const float*)d_in[0];
    const float* Wr1 = (const float*)d_in[1];
    const float* br1 = (const float*)d_in[2];
    const float* Wr2 = (const float*)d_in[3];
    const float* br2 = (const float*)d_in[4];
    const float* Ws1 = (const float*)d_in[5];
    const float* bs1 = (const float*)d_in[6];
    const float* Ws2 = (const float*)d_in[7];
    const float* bs2 = (const float*)d_in[8];
    const float* Wa1 = (const float*)d_in[9];
    const float* ba1 = (const float*)d_in[10];
    const float* Wa2 = (const float*)d_in[11];
    const float* ba2 = (const float*)d_in[12];
    const float* Wa3 = (const float*)d_in[13];
    const float* ba3 = (const float*)d_in[14];
    const int* fai = (const int*)d_in[15];
    const int* species = (const int*)d_in[16];
    float* out = (float*)d_out;

    // order chosen so ncu (captures launch #4) profiles k_atom
    k_edge<<<EDGES / 128, 128>>>(rij, Wr1, br1, Wr2, br2);
    k_seg<<<EDGES / 256, 256>>>(fai);
    k_group<<<1, 1024>>>(species);
    k_atom<<<NATOM, 128>>>();
    k_embS<<<NELEM, 32>>>(Ws1, bs1, Ws2, bs2);
    k_B<<<NFEAT, 256>>>(Wa1);
    k_head<<<MAXG, 256>>>(ba1, Wa2, ba2, Wa3, ba3);
    k_final<<<1, 32>>>(out);
}